// round 8
// baseline (speedup 1.0000x reference)
#include <cuda_runtime.h>
#include <cuda_fp16.h>
#include <cstdint>

// Problem constants
#define N_TOK  8192
#define IN_F   4096
#define OUT_F  4096
#define BLK    64
#define KBLK   16
#define TM     256    // token tile per CTA
// 4-stage pipeline, K=32 halves per stage (2 x k16 MMA steps)
#define STAGES 4
#define KS     32
#define LDH    40     // halves per smem row (80B stride; (5r+c)%8 permutation -> conflict-free)
#define ABYT   (TM * LDH * 2)     // 20480
#define BBYT   (BLK * LDH * 2)    // 5120
#define STGB   (ABYT + BBYT)      // 25600
#define SMEM_BYTES (STAGES * STGB) // 102400

// fp16 copies of x and w (converted each call)
__device__ __align__(16) __half g_xh[(size_t)N_TOK * IN_F];
__device__ __align__(16) __half g_wh[(size_t)BLK * KBLK * BLK * BLK];

__global__ void conv_all(const float4* __restrict__ x, const float4* __restrict__ w,
                         uint2* __restrict__ xh, uint2* __restrict__ wh,
                         int nx4, int nw4) {
    int i = blockIdx.x * blockDim.x + threadIdx.x;
    float4 v;
    uint2* o;
    if (i < nx4)           { v = x[i];       o = xh + i; }
    else if (i < nx4 + nw4){ v = w[i - nx4]; o = wh + (i - nx4); }
    else return;
    __half2 h0 = __floats2half2_rn(v.x, v.y);
    __half2 h1 = __floats2half2_rn(v.z, v.w);
    uint2 r; r.x = *(uint32_t*)&h0; r.y = *(uint32_t*)&h1;
    *o = r;
}

__device__ __forceinline__ void cp_async16(uint32_t saddr, const void* gptr) {
    asm volatile("cp.async.cg.shared.global [%0], [%1], 16;\n" :: "r"(saddr), "l"(gptr));
}
__device__ __forceinline__ void ldsm_x4(uint32_t& r0, uint32_t& r1, uint32_t& r2, uint32_t& r3,
                                        uint32_t saddr) {
    asm volatile("ldmatrix.sync.aligned.m8n8.x4.shared.b16 {%0,%1,%2,%3}, [%4];\n"
                 : "=r"(r0), "=r"(r1), "=r"(r2), "=r"(r3) : "r"(saddr));
}

__global__ __launch_bounds__(256, 2)
void bsl_f16_kernel(const float* __restrict__ bias,
                    const int*   __restrict__ col_idx,
                    float* __restrict__ out)
{
    extern __shared__ char smem[];
    const uint32_t sb0 = (uint32_t)__cvta_generic_to_shared(smem);
    const int rb  = blockIdx.x;        // output row-block (fast -> x L2 reuse)
    const int mti = blockIdx.y;
    const int m0  = mti * TM;
    const int n0  = rb * BLK;
    const int tid = threadIdx.x;

    const int lane = tid & 31;
    const int warp = tid >> 5;
    const int wm   = warp & 3;         // 4 warps along M -> 64 rows each
    const int wn   = warp >> 2;        // 2 warps along N -> 32 cols each
    const int qr   = lane >> 2;
    const int ql   = lane & 3;

    // loader mapping: 4 lanes per row, 16B chunk each (row data = 64B)
    const int lrow = tid >> 2;              // 0..63
    const int lchk = (tid & 3) * 8;         // halves
    const uint32_t a_dst0 = sb0 + (lrow * LDH + lchk) * 2;
    const uint32_t b_dst  = sb0 + ABYT + (lrow * LDH + lchk) * 2;

    // stage st covers block kb = st>>1, k-half (st&1)*32
    auto load_stage = [&](int st) {
        const int kb  = st >> 1;
        const int kof = (st & 1) * KS;
        const int col = __ldg(&col_idx[rb * KBLK + kb]) * BLK + kof;
        const uint32_t so = (st & (STAGES - 1)) * STGB;
        const __half* xg = g_xh + (size_t)(m0 + lrow) * IN_F + col + lchk;
        #pragma unroll
        for (int p = 0; p < 4; ++p)         // rows lrow + 64p
            cp_async16(a_dst0 + so + p * 64 * LDH * 2, xg + (size_t)p * 64 * IN_F);
        const __half* wg = g_wh + ((size_t)(rb * KBLK + kb) * BLK + lrow) * BLK + kof + lchk;
        cp_async16(b_dst + so, wg);
        asm volatile("cp.async.commit_group;\n");
    };

    float acc[4][4][4];
    #pragma unroll
    for (int i = 0; i < 4; ++i)
        #pragma unroll
        for (int j = 0; j < 4; ++j)
            #pragma unroll
            for (int r = 0; r < 4; ++r) acc[i][j][r] = 0.f;

    load_stage(0);
    load_stage(1);
    load_stage(2);

    // ldmatrix per-thread addressing (halves)
    const int a_row  = lane & 15;
    const int a_coff = (lane >> 4) * 8;
    const int b_row  = ((lane >> 4) << 3) + (lane & 7);
    const int b_coff = ((lane >> 3) & 1) * 8;
    uint32_t abase[4], bbase[2];
    #pragma unroll
    for (int i = 0; i < 4; ++i)
        abase[i] = sb0 + ((wm * 64 + i * 16 + a_row) * LDH + a_coff) * 2;
    #pragma unroll
    for (int jp = 0; jp < 2; ++jp)
        bbase[jp] = sb0 + ABYT + ((wn * 32 + jp * 16 + b_row) * LDH + b_coff) * 2;

    const int NST = KBLK * 2;              // 32 work stages
    for (int it = 0; it < NST; ++it) {
        if (it <= NST - 3)      asm volatile("cp.async.wait_group 2;\n");
        else if (it == NST - 2) asm volatile("cp.async.wait_group 1;\n");
        else                    asm volatile("cp.async.wait_group 0;\n");
        __syncthreads();

        if (it + 3 < NST) load_stage(it + 3);

        const uint32_t so = (it & (STAGES - 1)) * STGB;
        #pragma unroll
        for (int s = 0; s < 2; ++s) {       // 2 x k16 per stage
            const uint32_t koff = so + s * 32;   // bytes (16 halves)
            uint32_t a[4][4], b[4][2];
            #pragma unroll
            for (int i = 0; i < 4; ++i)
                ldsm_x4(a[i][0], a[i][1], a[i][2], a[i][3], abase[i] + koff);
            #pragma unroll
            for (int jp = 0; jp < 2; ++jp)
                ldsm_x4(b[2 * jp][0], b[2 * jp][1], b[2 * jp + 1][0], b[2 * jp + 1][1],
                        bbase[jp] + koff);
            #pragma unroll
            for (int i = 0; i < 4; ++i)
                #pragma unroll
                for (int j = 0; j < 4; ++j) {
                    asm volatile(
                        "mma.sync.aligned.m16n8k16.row.col.f32.f16.f16.f32 "
                        "{%0,%1,%2,%3}, {%4,%5,%6,%7}, {%8,%9}, {%0,%1,%2,%3};\n"
                        : "+f"(acc[i][j][0]), "+f"(acc[i][j][1]),
                          "+f"(acc[i][j][2]), "+f"(acc[i][j][3])
                        : "r"(a[i][0]), "r"(a[i][1]), "r"(a[i][2]), "r"(a[i][3]),
                          "r"(b[j][0]), "r"(b[j][1]));
                }
        }
    }

    // ---- epilogue: bias add + float2 stores ----
    #pragma unroll
    for (int j = 0; j < 4; ++j) {
        const int col = n0 + wn * 32 + j * 8 + 2 * ql;
        const float2 bv = *(const float2*)(bias + col);
        #pragma unroll
        for (int i = 0; i < 4; ++i) {
            const int row = m0 + wm * 64 + i * 16 + qr;
            float2 v0 = { acc[i][j][0] + bv.x, acc[i][j][1] + bv.y };
            *(float2*)(out + (size_t)row * OUT_F + col) = v0;
            float2 v1 = { acc[i][j][2] + bv.x, acc[i][j][3] + bv.y };
            *(float2*)(out + (size_t)(row + 8) * OUT_F + col) = v1;
        }
    }
}

extern "C" void kernel_launch(void* const* d_in, const int* in_sizes, int n_in,
                              void* d_out, int out_size)
{
    const float* x       = (const float*)d_in[0];
    const float* weight  = (const float*)d_in[1];
    const float* bias    = (const float*)d_in[2];
    // d_in[3] = row_idx (deterministic repeat(arange(64),16)) — unused
    const int*   col_idx = (const int*)d_in[4];
    float* out = (float*)d_out;

    __half* xh_p; cudaGetSymbolAddress((void**)&xh_p, g_xh);
    __half* wh_p; cudaGetSymbolAddress((void**)&wh_p, g_wh);
    const int nx4 = (N_TOK * IN_F) / 4;
    const int nw4 = (BLK * KBLK * BLK * BLK) / 4;
    conv_all<<<(nx4 + nw4) / 256, 256>>>((const float4*)x, (const float4*)weight,
                                         (uint2*)xh_p, (uint2*)wh_p, nx4, nw4);

    cudaFuncSetAttribute(bsl_f16_kernel,
                         cudaFuncAttributeMaxDynamicSharedMemorySize, SMEM_BYTES);
    dim3 grid(OUT_F / BLK, N_TOK / TM);   // (64, 32); rb fastest -> x L2 reuse
    bsl_f16_kernel<<<grid, 256, SMEM_BYTES>>>(bias, col_idx, out);
}

// round 9
// speedup vs baseline: 1.1021x; 1.1021x over previous
#include <cuda_runtime.h>
#include <cuda_fp16.h>
#include <cstdint>

// Problem constants
#define N_TOK  8192
#define IN_F   4096
#define OUT_F  4096
#define BLK    64
#define KBLK   16
#define TM     256    // token tile per CTA
#define LDH    72     // halves per smem row (144B stride -> conflict-free ldmatrix)
#define ABYT   (TM * LDH * 2)     // 36864
#define BBYT   (BLK * LDH * 2)    // 9216
#define BUFB   (ABYT + BBYT)      // 46080
#define SMEM_BYTES (2 * BUFB)     // 92160

// fp16 copies of x and w (converted each call)
__device__ __align__(16) __half g_xh[(size_t)N_TOK * IN_F];
__device__ __align__(16) __half g_wh[(size_t)BLK * KBLK * BLK * BLK];

__global__ void conv_all(const float4* __restrict__ x, const float4* __restrict__ w,
                         uint2* __restrict__ xh, uint2* __restrict__ wh,
                         int nx4, int nw4) {
    int i = blockIdx.x * blockDim.x + threadIdx.x;
    float4 v;
    uint2* o;
    if (i < nx4)            { v = x[i];       o = xh + i; }
    else if (i < nx4 + nw4) { v = w[i - nx4]; o = wh + (i - nx4); }
    else return;
    __half2 h0 = __floats2half2_rn(v.x, v.y);
    __half2 h1 = __floats2half2_rn(v.z, v.w);
    uint2 r; r.x = *(uint32_t*)&h0; r.y = *(uint32_t*)&h1;
    *o = r;
}

__device__ __forceinline__ void cp_async16(uint32_t saddr, const void* gptr) {
    asm volatile("cp.async.cg.shared.global [%0], [%1], 16;\n" :: "r"(saddr), "l"(gptr));
}
__device__ __forceinline__ void ldsm_x4(uint32_t& r0, uint32_t& r1, uint32_t& r2, uint32_t& r3,
                                        uint32_t saddr) {
    asm volatile("ldmatrix.sync.aligned.m8n8.x4.shared.b16 {%0,%1,%2,%3}, [%4];\n"
                 : "=r"(r0), "=r"(r1), "=r"(r2), "=r"(r3) : "r"(saddr));
}

// load all fragments for k-step s into slot c
#define LD_FRAGS(c, koff)                                                          \
    do {                                                                           \
        _Pragma("unroll")                                                          \
        for (int _i = 0; _i < 4; ++_i)                                             \
            ldsm_x4(a[c][_i][0], a[c][_i][1], a[c][_i][2], a[c][_i][3],            \
                    aaddr[_i] + (koff));                                           \
        _Pragma("unroll")                                                          \
        for (int _jp = 0; _jp < 2; ++_jp)                                          \
            ldsm_x4(b[c][2*_jp][0], b[c][2*_jp][1], b[c][2*_jp+1][0],              \
                    b[c][2*_jp+1][1], baddr[_jp] + (koff));                        \
    } while (0)

__global__ __launch_bounds__(256, 2)
void bsl_f16_kernel(const float* __restrict__ bias,
                    const int*   __restrict__ col_idx,
                    float* __restrict__ out)
{
    extern __shared__ char smem[];
    const uint32_t sb0 = (uint32_t)__cvta_generic_to_shared(smem);
    const int rb  = blockIdx.x;        // output row-block (fast -> x L2 reuse)
    const int mti = blockIdx.y;
    const int m0  = mti * TM;
    const int n0  = rb * BLK;
    const int tid = threadIdx.x;

    const int lane = tid & 31;
    const int warp = tid >> 5;
    const int wm   = warp & 3;         // 4 warps along M -> 64 rows each
    const int wn   = warp >> 2;        // 2 warps along N -> 32 cols each

    // ---- loader: 16B chunks, 8 per 64-half row ----
    const int lrow = tid >> 3;         // 0..31
    const int lchk = (tid & 7) * 8;
    auto load_block = [&](int kb, int buf) {
        const int col = __ldg(&col_idx[rb * KBLK + kb]) * BLK;
        const uint32_t so = buf * BUFB;
        const __half* xg = g_xh + (size_t)(m0 + lrow) * IN_F + col + lchk;
        const uint32_t sa = sb0 + so + (lrow * LDH + lchk) * 2;
        #pragma unroll
        for (int p = 0; p < 8; ++p)
            cp_async16(sa + p * 32 * LDH * 2, xg + (size_t)p * 32 * IN_F);
        const __half* wg = g_wh + (size_t)(rb * KBLK + kb) * (BLK * BLK) + lrow * BLK + lchk;
        const uint32_t sw = sb0 + so + ABYT + (lrow * LDH + lchk) * 2;
        #pragma unroll
        for (int p = 0; p < 2; ++p)
            cp_async16(sw + p * 32 * LDH * 2, wg + p * 32 * BLK);
        asm volatile("cp.async.commit_group;\n");
    };

    float acc[4][4][4];
    #pragma unroll
    for (int i = 0; i < 4; ++i)
        #pragma unroll
        for (int j = 0; j < 4; ++j)
            #pragma unroll
            for (int r = 0; r < 4; ++r) acc[i][j][r] = 0.f;

    load_block(0, 0);

    // ldmatrix per-thread addressing (halves)
    const int a_row  = lane & 15;
    const int a_coff = (lane >> 4) * 8;
    const int b_row  = ((lane >> 4) << 3) + (lane & 7);
    const int b_coff = ((lane >> 3) & 1) * 8;
    uint32_t aaddr0[4], baddr0[2];
    #pragma unroll
    for (int i = 0; i < 4; ++i)
        aaddr0[i] = sb0 + ((wm * 64 + i * 16 + a_row) * LDH + a_coff) * 2;
    #pragma unroll
    for (int jp = 0; jp < 2; ++jp)
        baddr0[jp] = sb0 + ABYT + ((wn * 32 + jp * 16 + b_row) * LDH + b_coff) * 2;

    for (int kb = 0; kb < KBLK; ++kb) {
        const int cur = kb & 1;
        if (kb < KBLK - 1) {
            load_block(kb + 1, cur ^ 1);
            asm volatile("cp.async.wait_group 1;\n");
        } else {
            asm volatile("cp.async.wait_group 0;\n");
        }
        __syncthreads();

        uint32_t aaddr[4], baddr[2];
        const uint32_t so = cur * BUFB;
        #pragma unroll
        for (int i = 0; i < 4; ++i) aaddr[i] = aaddr0[i] + so;
        #pragma unroll
        for (int jp = 0; jp < 2; ++jp) baddr[jp] = baddr0[jp] + so;

        uint32_t a[2][4][4], b[2][4][2];
        LD_FRAGS(0, 0);
        #pragma unroll
        for (int s = 0; s < 4; ++s) {          // K=64, 16 per MMA
            const int c = s & 1;
            if (s < 3) LD_FRAGS(c ^ 1, (s + 1) * 32);   // prefetch next step's frags
            #pragma unroll
            for (int i = 0; i < 4; ++i)
                #pragma unroll
                for (int j = 0; j < 4; ++j) {
                    asm volatile(
                        "mma.sync.aligned.m16n8k16.row.col.f32.f16.f16.f32 "
                        "{%0,%1,%2,%3}, {%4,%5,%6,%7}, {%8,%9}, {%0,%1,%2,%3};\n"
                        : "+f"(acc[i][j][0]), "+f"(acc[i][j][1]),
                          "+f"(acc[i][j][2]), "+f"(acc[i][j][3])
                        : "r"(a[c][i][0]), "r"(a[c][i][1]), "r"(a[c][i][2]), "r"(a[c][i][3]),
                          "r"(b[c][j][0]), "r"(b[c][j][1]));
                }
        }
        __syncthreads();
    }

    // ---- epilogue: bias add + float2 stores ----
    const int qr = lane >> 2, ql = lane & 3;
    #pragma unroll
    for (int j = 0; j < 4; ++j) {
        const int col = n0 + wn * 32 + j * 8 + 2 * ql;
        const float2 bv = *(const float2*)(bias + col);
        #pragma unroll
        for (int i = 0; i < 4; ++i) {
            const int row = m0 + wm * 64 + i * 16 + qr;
            float2 v0 = { acc[i][j][0] + bv.x, acc[i][j][1] + bv.y };
            *(float2*)(out + (size_t)row * OUT_F + col) = v0;
            float2 v1 = { acc[i][j][2] + bv.x, acc[i][j][3] + bv.y };
            *(float2*)(out + (size_t)(row + 8) * OUT_F + col) = v1;
        }
    }
}

extern "C" void kernel_launch(void* const* d_in, const int* in_sizes, int n_in,
                              void* d_out, int out_size)
{
    const float* x       = (const float*)d_in[0];
    const float* weight  = (const float*)d_in[1];
    const float* bias    = (const float*)d_in[2];
    // d_in[3] = row_idx (deterministic repeat(arange(64),16)) — unused
    const int*   col_idx = (const int*)d_in[4];
    float* out = (float*)d_out;

    __half* xh_p; cudaGetSymbolAddress((void**)&xh_p, g_xh);
    __half* wh_p; cudaGetSymbolAddress((void**)&wh_p, g_wh);
    const int nx4 = (N_TOK * IN_F) / 4;
    const int nw4 = (BLK * KBLK * BLK * BLK) / 4;
    conv_all<<<(nx4 + nw4) / 256, 256>>>((const float4*)x, (const float4*)weight,
                                         (uint2*)xh_p, (uint2*)wh_p, nx4, nw4);

    cudaFuncSetAttribute(bsl_f16_kernel,
                         cudaFuncAttributeMaxDynamicSharedMemorySize, SMEM_BYTES);
    dim3 grid(OUT_F / BLK, N_TOK / TM);   // (64, 32); rb fastest -> x L2 reuse
    bsl_f16_kernel<<<grid, 256, SMEM_BYTES>>>(bias, col_idx, out);
}